// round 11
// baseline (speedup 1.0000x reference)
#include <cuda_runtime.h>
#include <cuda_bf16.h>
#include <math.h>
#include <stdint.h>

#define TLEN  64
#define BSZ   32
#define NROWS 2048
#define HID   1024
#define SLEN  200
#define VTGT  32000
#define VEXT  2000
#define VOUT  34000
#define NT_N  125          // N tiles of 256

// ---------------------------------------------------------------------------
// device scratch
// ---------------------------------------------------------------------------
__device__ float g_logcopy[NROWS];
__device__ float g_omc[NROWS];
__device__ float2 g_part[(size_t)NROWS * NT_N];
__device__ __align__(128) __nv_bfloat16 g_Ahi[(size_t)NROWS * HID];
__device__ __align__(128) __nv_bfloat16 g_Bhi[(size_t)VTGT * HID];

// ---------------------------------------------------------------------------
// helpers
// ---------------------------------------------------------------------------
__device__ __forceinline__ uint32_t smem_u32(const void* p) {
    uint32_t a;
    asm("{ .reg .u64 t; cvta.to.shared.u64 t, %1; cvt.u32.u64 %0, t; }" : "=r"(a) : "l"(p));
    return a;
}
__device__ __forceinline__ void cp_async16(uint32_t dst, const void* src) {
    asm volatile("cp.async.cg.shared.global [%0], [%1], 16;" :: "r"(dst), "l"(src) : "memory");
}
#define CP_COMMIT() asm volatile("cp.async.commit_group;" ::: "memory")
#define CP_WAIT2()  asm volatile("cp.async.wait_group 2;" ::: "memory")

__device__ __forceinline__ void ldsm_x4(uint32_t* r, uint32_t addr) {
    asm volatile("ldmatrix.sync.aligned.m8n8.x4.shared.b16 {%0,%1,%2,%3}, [%4];"
                 : "=r"(r[0]), "=r"(r[1]), "=r"(r[2]), "=r"(r[3]) : "r"(addr));
}
__device__ __forceinline__ void mma_bf16(float* c, const uint32_t* a, uint32_t b0, uint32_t b1) {
    asm volatile(
        "mma.sync.aligned.m16n8k16.row.col.f32.bf16.bf16.f32 "
        "{%0,%1,%2,%3}, {%4,%5,%6,%7}, {%8,%9}, {%0,%1,%2,%3};"
        : "+f"(c[0]), "+f"(c[1]), "+f"(c[2]), "+f"(c[3])
        : "r"(a[0]), "r"(a[1]), "r"(a[2]), "r"(a[3]), "r"(b0), "r"(b1));
}

// ---------------------------------------------------------------------------
// pack: fp32 -> bf16 (round-to-nearest)
// ---------------------------------------------------------------------------
__global__ __launch_bounds__(256) void pack_hi(const float* __restrict__ src,
                                               __nv_bfloat16* __restrict__ hi,
                                               int n4) {
    int stride = gridDim.x * blockDim.x;
    for (int i = blockIdx.x * blockDim.x + threadIdx.x; i < n4; i += stride) {
        float4 v = ((const float4*)src)[i];
        ushort4 h;
        unsigned short* hp = (unsigned short*)&h;
        hp[0] = __bfloat16_as_ushort(__float2bfloat16(v.x));
        hp[1] = __bfloat16_as_ushort(__float2bfloat16(v.y));
        hp[2] = __bfloat16_as_ushort(__float2bfloat16(v.z));
        hp[3] = __bfloat16_as_ushort(__float2bfloat16(v.w));
        ((ushort4*)hi)[i] = h;
    }
}

// ---------------------------------------------------------------------------
// GEMM: out[m, n] = A[m,:] . B[n,:] + bias[n]   (+ per-(row,ntile) softmax partials)
// BM=128, BN=256, BK=64, 512 threads (16 warps: 4M x 4N, warp tile 32x64)
// pure bf16 ; 4 stages, 16 stage-iterations, mainloop unrolled x4
// stage smem: A 128x144B (18432) | B 256x144B (36864) = 55296B  (144B row stride)
// ---------------------------------------------------------------------------
#define RSTR      144
#define BOFF      18432
#define STAGE_B   55296
#define SMEM_GEMM (4 * STAGE_B)
#define NSTAGE    16

__global__ __launch_bounds__(512, 1) void gemm_mma(const float* __restrict__ bias,
                                                   float* __restrict__ out) {
    extern __shared__ unsigned char smem[];
    const uint32_t sb = smem_u32(smem);
    const int tid = threadIdx.x;
    const int wid = tid >> 5, lid = tid & 31;
    const int wm = wid & 3;          // 0..3  (32-row slice)
    const int wn = wid >> 2;         // 0..3  (64-col slice)
    const int m0 = blockIdx.x * 128;
    const int n0 = blockIdx.y * 256;

    // persistent per-thread cp.async state: 6 chunks/thread/stage
    // A rows r, r+64; B rows r, r+64, r+128, r+192; col = tid&7 (8 bf16 per chunk)
    const int r  = tid >> 3, c = tid & 7;
    const uint32_t dA = (uint32_t)r * RSTR + c * 16;
    const uint32_t dB = BOFF + (uint32_t)r * RSTR + c * 16;
    const __nv_bfloat16* pA = g_Ahi + (size_t)(m0 + r) * HID + c * 8;
    const __nv_bfloat16* pB = g_Bhi + (size_t)(n0 + r) * HID + c * 8;

#define ISSUE(bufc) do {                                               \
        const uint32_t d = sb + (bufc) * STAGE_B;                      \
        cp_async16(d + dA,          pA);                               \
        cp_async16(d + dA + 9216,   pA + (size_t)64 * HID);            \
        cp_async16(d + dB,          pB);                               \
        cp_async16(d + dB + 9216,   pB + (size_t)64 * HID);            \
        cp_async16(d + dB + 18432,  pB + (size_t)128 * HID);           \
        cp_async16(d + dB + 27648,  pB + (size_t)192 * HID);           \
        pA += 64; pB += 64;                                            \
    } while (0)

    float acc[2][8][4] = {};

    ISSUE(0); CP_COMMIT();
    ISSUE(1); CP_COMMIT();
    ISSUE(2); CP_COMMIT();

    const int lrow = lid & 15;
    const int lcol = (lid >> 4) << 3;     // 0 or 8
    const uint32_t a_row_off = (uint32_t)(wm * 32 + lrow) * RSTR;
    const uint32_t b_row_off = BOFF + (uint32_t)(wn * 64 + lrow) * RSTR;

#define COMPUTE(bufc) do {                                                          \
        const uint32_t st = sb + (bufc) * STAGE_B;                                  \
        _Pragma("unroll")                                                           \
        for (int kk = 0; kk < 64; kk += 16) {                                       \
            const uint32_t coff = (uint32_t)(kk + lcol) * 2;                        \
            uint32_t ah[2][4], bh[4][4];                                            \
            _Pragma("unroll")                                                       \
            for (int mi = 0; mi < 2; mi++)                                          \
                ldsm_x4(ah[mi], st + a_row_off + (uint32_t)(mi * 16) * RSTR + coff);\
            _Pragma("unroll")                                                       \
            for (int g = 0; g < 4; g++)                                             \
                ldsm_x4(bh[g], st + b_row_off + (uint32_t)(g * 16) * RSTR + coff);  \
            _Pragma("unroll")                                                       \
            for (int mi = 0; mi < 2; mi++)                                          \
                _Pragma("unroll")                                                   \
                for (int g = 0; g < 4; g++)                                         \
                    _Pragma("unroll")                                               \
                    for (int j = 0; j < 2; j++)                                     \
                        mma_bf16(acc[mi][2 * g + j], ah[mi], bh[g][j], bh[g][2 + j]); \
        }                                                                           \
    } while (0)

#define BODY(s, j) do {                                     \
        CP_WAIT2();                                         \
        __syncthreads();                                    \
        if ((s) + (j) + 3 < NSTAGE) ISSUE(((j) + 3) & 3);   \
        CP_COMMIT();                                        \
        COMPUTE(j);                                         \
    } while (0)

    for (int s = 0; s < NSTAGE; s += 4) {
        BODY(s, 0);
        BODY(s, 1);
        BODY(s, 2);
        BODY(s, 3);
    }

    // ---- epilogue: bias add + store + per-row softmax partials ----
    const int qrow = lid >> 2;
    const int qcol = (lid & 3) * 2;
#pragma unroll
    for (int ni = 0; ni < 8; ni++) {
        const int gn = n0 + wn * 64 + ni * 8 + qcol;
        const float b0 = __ldg(&bias[gn]);
        const float b1 = __ldg(&bias[gn + 1]);
#pragma unroll
        for (int mi = 0; mi < 2; mi++) {
            const int gm = m0 + wm * 32 + mi * 16 + qrow;
            acc[mi][ni][0] += b0; acc[mi][ni][1] += b1;
            acc[mi][ni][2] += b0; acc[mi][ni][3] += b1;
            *(float2*)&out[(size_t)gm * VOUT + gn] = make_float2(acc[mi][ni][0], acc[mi][ni][1]);
            *(float2*)&out[(size_t)(gm + 8) * VOUT + gn] = make_float2(acc[mi][ni][2], acc[mi][ni][3]);
        }
    }

    // per-row (max, sum exp) over this CTA's 256-col slice
    __syncthreads();
    float2* sm2 = (float2*)smem;
#pragma unroll
    for (int mi = 0; mi < 2; mi++)
#pragma unroll
        for (int h = 0; h < 2; h++) {
            float m = -1e30f;
#pragma unroll
            for (int ni = 0; ni < 8; ni++)
                m = fmaxf(m, fmaxf(acc[mi][ni][2 * h], acc[mi][ni][2 * h + 1]));
            float s = 0.f;
#pragma unroll
            for (int ni = 0; ni < 8; ni++)
                s += __expf(acc[mi][ni][2 * h] - m) + __expf(acc[mi][ni][2 * h + 1] - m);
#pragma unroll
            for (int o = 1; o <= 2; o <<= 1) {
                float om = __shfl_xor_sync(0xffffffffu, m, o);
                float os = __shfl_xor_sync(0xffffffffu, s, o);
                float nm = fmaxf(m, om);
                s = s * __expf(m - nm) + os * __expf(om - nm);
                m = nm;
            }
            if ((lid & 3) == 0)
                sm2[(wm * 32 + mi * 16 + h * 8 + qrow) * 4 + wn] = make_float2(m, s);
        }
    __syncthreads();
    if (tid < 128) {
        float m = -1e30f, s = 0.f;
#pragma unroll
        for (int w = 0; w < 4; w++) {
            float2 p = sm2[tid * 4 + w];
            float nm = fmaxf(m, p.x);
            s = s * __expf(m - nm) + p.y * __expf(p.x - nm);
            m = nm;
        }
        g_part[(size_t)(m0 + tid) * NT_N + blockIdx.y] = make_float2(m, s);
    }
}

// ---------------------------------------------------------------------------
// copy gate: one warp per row
// ---------------------------------------------------------------------------
__global__ void copy_gate_kernel(const float* __restrict__ h,
                                 const float* __restrict__ w_copy,
                                 const float* __restrict__ b_copy) {
    int warp = (blockIdx.x * blockDim.x + threadIdx.x) >> 5;
    int lane = threadIdx.x & 31;
    if (warp >= NROWS) return;
    const float* hr = h + (size_t)warp * HID;
    float s = 0.f;
#pragma unroll 8
    for (int i = lane; i < HID; i += 32) s += hr[i] * w_copy[i];
#pragma unroll
    for (int off = 16; off; off >>= 1) s += __shfl_xor_sync(0xffffffffu, s, off);
    if (lane == 0) {
        float z = s + b_copy[0];
        float c = 1.f / (1.f + expf(-z));
        g_logcopy[warp] = logf(fminf(fmaxf(c, 0.001f), 0.999f));
        g_omc[warp]     = 1.f - c;
    }
}

// ---------------------------------------------------------------------------
// softmax finalize: reduce 125 partials per row, then add-sweep
// ---------------------------------------------------------------------------
__global__ __launch_bounds__(256) void softmax_fin(float* __restrict__ out) {
    const int row = blockIdx.x;
    const int tid = threadIdx.x;
    __shared__ float rm[256], rs[256];

    float m = -1e30f, s = 0.f;
    if (tid < NT_N) {
        float2 p = g_part[(size_t)row * NT_N + tid];
        m = p.x; s = p.y;
    }
    rm[tid] = m; rs[tid] = s;
    __syncthreads();
#pragma unroll
    for (int st = 128; st; st >>= 1) {
        if (tid < st) {
            float m2 = rm[tid + st], s2 = rs[tid + st];
            float nm = fmaxf(rm[tid], m2);
            rs[tid] = rs[tid] * __expf(rm[tid] - nm) + s2 * __expf(m2 - nm);
            rm[tid] = nm;
        }
        __syncthreads();
    }
    const float add = g_logcopy[row] - (rm[0] + logf(rs[0]));

    float4* q4 = (float4*)(out + (size_t)row * VOUT);
    for (int v = tid; v < VTGT / 4; v += 256) {
        float4 x = q4[v];
        x.x += add; x.y += add; x.z += add; x.w += add;
        q4[v] = x;
    }
}

// ---------------------------------------------------------------------------
// ext-vocab scatter
// ---------------------------------------------------------------------------
__global__ __launch_bounds__(256) void ext_kernel(const float* __restrict__ attn,
                                                  const int* __restrict__ c2e,
                                                  float* __restrict__ out) {
    const int row = blockIdx.x;
    const int b   = row & (BSZ - 1);
    const int tid = threadIdx.x;
    __shared__ float ext[VEXT];

    for (int e = tid; e < VEXT; e += 256) ext[e] = 0.f;
    __syncthreads();

    const float omc = g_omc[row];
    for (int s = tid; s < SLEN; s += 256) {
        int idx = c2e[s * BSZ + b];
        if (idx != 0)
            atomicAdd(&ext[idx], attn[(size_t)row * SLEN + s] * omc);
    }
    __syncthreads();

    float* p = out + (size_t)row * VOUT + VTGT;
    for (int e = tid; e < VEXT; e += 256)
        p[e] = logf(fminf(fmaxf(ext[e], 0.001f), 0.999f));
}

// ---------------------------------------------------------------------------
extern "C" void kernel_launch(void* const* d_in, const int* in_sizes, int n_in,
                              void* d_out, int out_size) {
    const float* hidden  = (const float*)d_in[0];
    const float* attn    = (const float*)d_in[1];
    const int*   c2e     = (const int*)  d_in[2];
    const float* W_out   = (const float*)d_in[3];
    const float* b_out   = (const float*)d_in[4];
    const float* w_copy  = (const float*)d_in[5];
    const float* b_copy  = (const float*)d_in[6];
    float* out = (float*)d_out;

    __nv_bfloat16 *Ahi, *Bhi;
    cudaGetSymbolAddress((void**)&Ahi, g_Ahi);
    cudaGetSymbolAddress((void**)&Bhi, g_Bhi);

    cudaFuncSetAttribute(gemm_mma, cudaFuncAttributeMaxDynamicSharedMemorySize, SMEM_GEMM);

    copy_gate_kernel<<<NROWS / 8, 256>>>(hidden, w_copy, b_copy);
    pack_hi<<<256, 256>>>(hidden, Ahi, NROWS * HID / 4);
    pack_hi<<<2048, 256>>>(W_out, Bhi, VTGT * HID / 4);
    gemm_mma<<<dim3(NROWS / 128, VTGT / 256), 512, SMEM_GEMM>>>(b_out, out);
    ext_kernel<<<NROWS, 256>>>(attn, c2e, out);
    softmax_fin<<<NROWS, 256>>>(out);
}